// round 16
// baseline (speedup 1.0000x reference)
#include <cuda_runtime.h>
#include <cstdint>

#define NC  5
#define TPB 256
#define NBLK 1024   // 1024*256 threads; 8 rows/thread at n = 2,097,152

__device__ __forceinline__ float fast_ex2(float x) {
    float y; asm("ex2.approx.f32 %0, %1;" : "=f"(y) : "f"(x)); return y;
}
__device__ __forceinline__ float fast_lg2(float x) {
    float y; asm("lg2.approx.f32 %0, %1;" : "=f"(y) : "f"(x)); return y;
}
__device__ __forceinline__ float fast_rcp(float x) {
    float y; asm("rcp.approx.f32 %0, %1;" : "=f"(y) : "f"(x)); return y;
}
__device__ __forceinline__ float fast_rsq(float x) {
    float y; asm("rsqrt.approx.f32 %0, %1;" : "=f"(y) : "f"(x)); return y;
}

// h(t) = t*mu(t) - log2 Z(t) + C2 (log2 domain), C2=(ln5-eps)/ln2, increasing.
// p(t) = softmax(t * log2 q). Feasible (lam=0) iff h(1) <= 0, then p = q/sum(q).
#define C2CONST 2.1776498f     // (ln5 - 0.1)/ln2
#define LN2SQ   0.48045302f    // ln2^2
#define LN2CU   0.33302465f    // ln2^3
#define RLN2    1.44269504f    // 1/ln2
#define SQ2EPS  0.44721360f    // sqrt(2*eps)

// Solve h(t)=0 on (0,1): cubic-Taylor init + 3 safeguarded Newton steps.
__device__ __forceinline__ float solve_row(const float L[NC]) {
    float s1 = 0.f, s2 = 0.f, s3 = 0.f;
    #pragma unroll
    for (int j = 0; j < NC; j++) {
        float lj = L[j];
        s1 += lj; s2 = fmaf(lj, lj, s2); s3 = fmaf(lj * lj, lj, s3);
    }
    float m   = s1 * 0.2f;
    float e2  = s2 * 0.2f;
    float V   = fmaxf(LN2SQ * (e2 - m * m), 1e-9f);
    float m3  = LN2CU * fmaf(s3, 0.2f, fmaf(-3.f * m, e2, 2.f * m * m * m));
    float tl  = SQ2EPS * fast_rsq(V);
    float den = fmaxf(fmaf(0.6666667f * m3, tl, V), 1e-9f);
    float tc  = fminf(0.95f, fmaxf(SQ2EPS * fast_rsq(den), 1e-4f));

    float lo = 0.f, hi = 1.f;
    #pragma unroll
    for (int it = 0; it < 3; ++it) {
        float S = 0.f, A = 0.f, B = 0.f;
        #pragma unroll
        for (int j = 0; j < NC; j++) {
            float e  = fast_ex2(tc * L[j]);
            float el = e * L[j];
            S += e; A = fmaf(e, L[j], A); B = fmaf(el, L[j], B);
        }
        float r  = fast_rcp(S);
        float mu = A * r;
        float v  = fmaf(B, r, -(mu * mu));
        float h  = fmaf(tc, mu, C2CONST - fast_lg2(S));
        float hp = tc * v;
        bool pos = (h > 0.f);
        hi = pos ? tc : hi;
        lo = pos ? lo : tc;
        float tn = fmaf(-h * RLN2, fast_rcp(hp), tc);
        bool ok = (tn > lo) && (tn < hi);   // false also on NaN
        tc = ok ? tn : 0.5f * (lo + hi);
    }
    return tc;
}

// Persistent grid-stride kernel, prefetch distance 2 (triple buffer):
// loads for iteration i+2 are in flight while iterations i, i+1 compute.
__global__ void __launch_bounds__(TPB) kl_proj_persist(
    const float* __restrict__ x,
    const float* __restrict__ W,
    const float* __restrict__ b,
    float* __restrict__ out,
    int n)
{
    __shared__ float sW[NC * NC];
    __shared__ float sb[NC];
    if (threadIdx.x < NC * NC) sW[threadIdx.x] = W[threadIdx.x];
    if (threadIdx.x < NC)      sb[threadIdx.x] = b[threadIdx.x];
    __syncthreads();

    const int stride = gridDim.x * blockDim.x;
    int row = blockIdx.x * blockDim.x + threadIdx.x;

    float b0[NC], b1[NC];
    bool h0 = (row < n);
    bool h1 = (row + stride < n);
    if (h0) {
        #pragma unroll
        for (int k = 0; k < NC; k++) b0[k] = x[(size_t)row * NC + k];
    }
    if (h1) {
        #pragma unroll
        for (int k = 0; k < NC; k++) b1[k] = x[(size_t)(row + stride) * NC + k];
    }

    while (h0) {
        // ---- Prefetch iteration i+2 (lands while i and i+1 compute) ----
        int  prow = row + 2 * stride;
        bool hp   = (prow < n);
        float b2[NC];
        if (hp) {
            #pragma unroll
            for (int k = 0; k < NC; k++) b2[k] = x[(size_t)prow * NC + k];
        }

        // ---- Compute current row ----
        // q = x W^T + b, q in [0.1, 3.1] -> lg2/ex2 safe, no max-shift.
        float q[NC];
        float s = 0.f, A = 0.f;
        #pragma unroll
        for (int j = 0; j < NC; j++) {
            float qq = sb[j];
            #pragma unroll
            for (int k = 0; k < NC; k++) qq = fmaf(b0[k], sW[j * NC + k], qq);
            q[j] = qq;
            s += qq;
            A = fmaf(qq, fast_lg2(qq), A);    // lg2 transient
        }
        float ir = fast_rcp(s);
        float h1v = A * ir - fast_lg2(s) + C2CONST;
        bool feas = (h1v <= 0.f);

        // Rare solver branch (warp-vote-guarded).
        if (!__all_sync(__activemask(), feas)) {
            if (!feas) {
                float L[NC];
                #pragma unroll
                for (int j = 0; j < NC; j++) L[j] = fast_lg2(q[j]);
                float t = solve_row(L);
                float S = 0.f;
                #pragma unroll
                for (int j = 0; j < NC; j++) { q[j] = fast_ex2(t * L[j]); S += q[j]; }
                ir = fast_rcp(S);
            }
        }

        // t = 1 shortcut exact: p = q / sum(q). No ex2 on the common path.
        #pragma unroll
        for (int j = 0; j < NC; j++) out[(size_t)row * NC + j] = q[j] * ir;

        // ---- Rotate pipeline ----
        row += stride;
        h0 = h1;
        h1 = hp;
        #pragma unroll
        for (int k = 0; k < NC; k++) { b0[k] = b1[k]; b1[k] = b2[k]; }
    }
}

extern "C" void kernel_launch(void* const* d_in, const int* in_sizes, int n_in,
                              void* d_out, int out_size) {
    const float* x = (const float*)d_in[0];
    const float* W = (const float*)d_in[1];
    const float* b = (const float*)d_in[2];
    float* out = (float*)d_out;
    int n = in_sizes[0] / NC;   // 2,097,152 rows

    kl_proj_persist<<<NBLK, TPB>>>(x, W, b, out, n);
}